// round 12
// baseline (speedup 1.0000x reference)
#include <cuda_runtime.h>
#include <cstdint>

// Spatial correlation sampler: out[b, dh*9+dw, h, w] =
//   (1/C) * sum_c in1[b,c,h,w] * in2[b,c,h+dh-4,w+dw-4]   (zero-padded)
// B=8, C=256, H=128, W=256, patch=9.
//
// R12 = R11 (288-thread CTAs, tile 8x16, 2 CTAs/SM, warp=dh) with CCH=8 and
// ring-3: 32 stages instead of 64 -> half the barriers and loader overhead.
// Loader = 4 hoisted cp.async slots per thread. 86KB dynamic smem per CTA.

#define BB   8
#define CC_  256
#define HH   128
#define WW   256
#define RAD  4
#define PATCH 9

#define TH   8
#define TW   16
#define CCH  8                        // channels per stage
#define NSTAGE 3                      // ring depth
#define NSLOT 4                       // loader chunks per thread
#define ROWS2 (TH + 2*RAD)            // 16 in2 rows
#define P2   48                       // in2 row pitch (floats); 24 used; 12 chunks
#define P1   16                       // in1 row pitch (floats)
#define IN2F (ROWS2 * P2)             // 768
#define CHF  (IN2F + TH * P1)         // 896 floats per channel
#define STAGEF (CCH * CHF)            // 7168 floats
#define STAGE_B (STAGEF * 4)          // 28672 bytes
#define RING_B (NSTAGE * STAGE_B)     // 86016 bytes
#define IN2CK (ROWS2 * 6)             // 96 chunks per channel (in2)
#define CHCK  (IN2CK + TH * 4)        // 128 chunks per channel
#define TOTCK (CCH * CHCK)            // 1024 chunks per stage
#define NT    288
#define NSTEPS (CC_ / CCH)            // 32 stages

__device__ __forceinline__ unsigned smem_u32(const void* p) {
    return (unsigned)__cvta_generic_to_shared(p);
}
__device__ __forceinline__ void cp16(unsigned dst, const void* src, int src_bytes) {
    asm volatile("cp.async.cg.shared.global [%0], [%1], 16, %2;\n"
                 :: "r"(dst), "l"(src), "r"(src_bytes));
}

__global__ void __launch_bounds__(NT, 2)
corr_kernel(const float* __restrict__ in1,
            const float* __restrict__ in2,
            float* __restrict__ out)
{
    extern __shared__ __align__(16) float sm[];          // RING_B bytes dynamic

    const int tid  = threadIdx.x;
    const int lane = tid & 31;
    const int wg   = lane & 3;        // 4 w-groups x 4 px = 16 w
    const int hh   = lane >> 2;       // 0..7 rows
    const int dh   = tid >> 5;        // warp id = displacement row 0..8

    const int w0 = blockIdx.x * TW;
    const int h0 = blockIdx.y * TH;
    const int b  = blockIdx.z;

    const float* __restrict__ in1b = in1 + (size_t)b * CC_ * HH * WW;
    const float* __restrict__ in2b = in2 + (size_t)b * CC_ * HH * WW;

    // ---- hoisted loader slots (decoded once; per stage just advance) ----
    const unsigned smbase = smem_u32(sm);
    const unsigned smend  = smbase + RING_B;

    const float* src[NSLOT];
    unsigned dst[NSLOT];
    int      sz[NSLOT];
    bool     val[NSLOT];

    auto decode = [&](int i, const float*& s_, unsigned& d_, int& z_) {
        int ch = i >> 7;                   // CHCK = 128
        int r  = i & 127;
        z_ = 16;
        if (r < IN2CK) {
            int row = r / 6;
            int ck  = r - row * 6;
            int gh = h0 - RAD + row;
            int gw = w0 - RAD + ck * 4;    // chunk fully in or fully out
            d_ = smbase + (unsigned)(ch * CHF + row * P2 + ck * 4) * 4u;
            if (gh < 0 || gh >= HH || gw < 0 || gw >= WW) {
                z_ = 0; s_ = in2b;         // full-chunk zero fill each stage
            } else {
                s_ = in2b + ((size_t)ch * HH + gh) * WW + gw;
            }
        } else {
            int r2 = r - IN2CK;
            int row = r2 >> 2;
            int ck  = r2 & 3;
            d_ = smbase + (unsigned)(ch * CHF + IN2F + row * P1 + ck * 4) * 4u;
            s_ = in1b + ((size_t)ch * HH + (h0 + row)) * WW + (w0 + ck * 4);
        }
    };

#pragma unroll
    for (int t = 0; t < NSLOT; t++) {
        int i = tid + t * NT;
        val[t] = (i < TOTCK);
        if (val[t]) decode(i, src[t], dst[t], sz[t]);
        else { src[t] = in2b; dst[t] = smbase; sz[t] = 0; }
    }

    const size_t src_step = (size_t)CCH * HH * WW;   // floats per stage

    auto load_stage = [&]() {
#pragma unroll
        for (int t = 0; t < NSLOT; t++) {
            if (val[t]) {
                cp16(dst[t], src[t], sz[t]);
                src[t] += src_step;
                dst[t] += STAGE_B; if (dst[t] >= smend) dst[t] -= RING_B;
            }
        }
        asm volatile("cp.async.commit_group;\n");
    };

    // ---- accumulators ----
    float acc[PATCH][4];
#pragma unroll
    for (int dw = 0; dw < PATCH; dw++)
#pragma unroll
        for (int j = 0; j < 4; j++) acc[dw][j] = 0.0f;

    const int off_win = (hh + dh) * P2 + wg * 4;     // window floats [0..12)
    const int off_a   = IN2F + hh * P1 + wg * 4;

    load_stage();   // stage 0 -> slot 0
    load_stage();   // stage 1 -> slot 1

    const float* buf = sm;
    for (int s = 0; s < NSTEPS; s++) {
        asm volatile("cp.async.wait_group 1;\n");        // my stage-s chunks done
        __syncthreads();                                  // publish all warps' stage s
        if (s + 2 < NSTEPS) load_stage();                 // stage s+2 -> freed slot
        else asm volatile("cp.async.commit_group;\n");    // keep group accounting

#pragma unroll
        for (int cc = 0; cc < CCH; cc++) {
            const float* chp = buf + cc * CHF;
            const float4 a4 = *(const float4*)(chp + off_a);
            const float4* wp = (const float4*)(chp + off_win);
            float4 x0 = wp[0], x1 = wp[1], x2 = wp[2];
            float win[12] = { x0.x, x0.y, x0.z, x0.w,
                              x1.x, x1.y, x1.z, x1.w,
                              x2.x, x2.y, x2.z, x2.w };
            float a[4] = { a4.x, a4.y, a4.z, a4.w };
#pragma unroll
            for (int dw = 0; dw < PATCH; dw++)
#pragma unroll
                for (int j = 0; j < 4; j++)
                    acc[dw][j] = fmaf(a[j], win[j + dw], acc[dw][j]);
        }

        buf += STAGEF;
        if (buf >= sm + NSTAGE * STAGEF) buf = sm;
    }

    // ---- epilogue ----
    const float scale = 1.0f / (float)CC_;
    float* outp = out + (((size_t)b * (PATCH * PATCH) + dh * PATCH) * HH + (h0 + hh)) * WW
                      + (w0 + wg * 4);
#pragma unroll
    for (int dw = 0; dw < PATCH; dw++) {
        float4 v;
        v.x = acc[dw][0] * scale;
        v.y = acc[dw][1] * scale;
        v.z = acc[dw][2] * scale;
        v.w = acc[dw][3] * scale;
        *(float4*)(outp + (size_t)dw * HH * WW) = v;
    }
}

extern "C" void kernel_launch(void* const* d_in, const int* in_sizes, int n_in,
                              void* d_out, int out_size)
{
    const float* in1 = (const float*)d_in[0];
    const float* in2 = (const float*)d_in[1];
    float* out = (float*)d_out;

    cudaFuncSetAttribute(corr_kernel,
                         cudaFuncAttributeMaxDynamicSharedMemorySize, RING_B);

    dim3 grid(WW / TW, HH / TH, BB);   // 16 x 16 x 8 = 2048 blocks
    dim3 block(NT);
    corr_kernel<<<grid, block, RING_B>>>(in1, in2, out);
}